// round 16
// baseline (speedup 1.0000x reference)
#include <cuda_runtime.h>
#include <cuda_bf16.h>
#include <cstdint>

// Problem constants
#define B_ROWS   8192
#define D_IN     768
#define D_HID    12288
#define TOPK_K   64
#define NCAND    128
#define WANT     72

// Output layout (floats): x_hat, residual, h, f, indices, pre_acts
#define XHAT_OFF 0LL
#define RES_OFF  6291456LL
#define H_OFF    12582912LL
#define F_OFF    113246208LL
#define IDX_OFF  213909504LL
#define PRE_OFF  214433792LL

// -------------------- device scratch --------------------
__device__ float g_WdT[(size_t)D_HID * D_IN];
__device__ int   g_cand[(size_t)B_ROWS * NCAND];
__device__ int   g_ccnt[B_ROWS];
// bf16 split operands for tensor-core encode GEMM
__device__ __nv_bfloat16 g_Xhi[(size_t)B_ROWS * D_IN];
__device__ __nv_bfloat16 g_Xlo[(size_t)B_ROWS * D_IN];
__device__ __nv_bfloat16 g_Whi[(size_t)D_HID * D_IN];
__device__ __nv_bfloat16 g_Wlo[(size_t)D_HID * D_IN];

// -------------------- helpers --------------------
__device__ __forceinline__ uint32_t smem_u32(const void* p) {
    uint32_t a;
    asm("{ .reg .u64 t; cvta.to.shared.u64 t, %1; cvt.u32.u64 %0, t; }" : "=r"(a) : "l"(p));
    return a;
}
#define CP16(dst, src) \
    asm volatile("cp.async.cg.shared.global [%0], [%1], 16;" :: "r"(dst), "l"(src) : "memory")
#define CP_COMMIT() asm volatile("cp.async.commit_group;" ::: "memory")

__device__ __forceinline__ void ldsm_x4(unsigned* r, uint32_t addr) {
    asm volatile("ldmatrix.sync.aligned.m8n8.x4.shared.b16 {%0,%1,%2,%3}, [%4];"
                 : "=r"(r[0]), "=r"(r[1]), "=r"(r[2]), "=r"(r[3]) : "r"(addr));
}
__device__ __forceinline__ void mma16816(float* c, const unsigned* a, const unsigned* b) {
    asm volatile(
        "mma.sync.aligned.m16n8k16.row.col.f32.bf16.bf16.f32 "
        "{%0,%1,%2,%3}, {%4,%5,%6,%7}, {%8,%9}, {%0,%1,%2,%3};"
        : "+f"(c[0]), "+f"(c[1]), "+f"(c[2]), "+f"(c[3])
        : "r"(a[0]), "r"(a[1]), "r"(a[2]), "r"(a[3]), "r"(b[0]), "r"(b[1]));
}

// -------------------- K0a: bf16 split conversions --------------------
__global__ void convertX_kernel(const float* __restrict__ x,
                                const float* __restrict__ pre_bias) {
    const int row = blockIdx.x;
    for (int c = threadIdx.x; c < D_IN; c += 256) {
        float v = x[(size_t)row * D_IN + c] - pre_bias[c];
        __nv_bfloat16 hi = __float2bfloat16(v);
        float lo = v - __bfloat162float(hi);
        size_t o = (size_t)row * D_IN + c;
        g_Xhi[o] = hi;
        g_Xlo[o] = __float2bfloat16(lo);
    }
}
__global__ void convertW_kernel(const float* __restrict__ w) {
    const int row = blockIdx.x;
    for (int c = threadIdx.x; c < D_IN; c += 256) {
        float v = w[(size_t)row * D_IN + c];
        __nv_bfloat16 hi = __float2bfloat16(v);
        float lo = v - __bfloat162float(hi);
        size_t o = (size_t)row * D_IN + c;
        g_Whi[o] = hi;
        g_Wlo[o] = __float2bfloat16(lo);
    }
}

// -------------------- K0b: transpose W_dec -> g_WdT --------------------
__global__ void transpose_kernel(const float* __restrict__ Wd) {
    __shared__ float tile[32][33];
    int x = blockIdx.x * 32 + threadIdx.x;
    int y = blockIdx.y * 32 + threadIdx.y;
    #pragma unroll
    for (int i = 0; i < 32; i += 8)
        tile[threadIdx.y + i][threadIdx.x] = Wd[(size_t)(y + i) * D_HID + x];
    __syncthreads();
    int xo = blockIdx.y * 32 + threadIdx.x;
    int yo = blockIdx.x * 32 + threadIdx.y;
    #pragma unroll
    for (int i = 0; i < 32; i += 8)
        g_WdT[(size_t)(yo + i) * D_IN + xo] = tile[threadIdx.x][threadIdx.y + i];
}

// -------------------- K1: HMMA encode GEMM (unchanged from R14/R15) -----------------------
#define SMS    40
#define ARR    10240
#define BUFB   40960
#define NCH    24

__global__ __launch_bounds__(256, 2)
void gemm_mma_kernel(const float* __restrict__ latent_bias,
                     float* __restrict__ out) {
    extern __shared__ char dsm[];
    float* sbias = (float*)dsm;
    const uint32_t bufs = smem_u32(dsm) + 1024;

    const int tid = threadIdx.x;
    const int warp = tid >> 5, lane = tid & 31;
    const int g = lane >> 2, tig = lane & 3;
    const int wm = warp >> 2, wn = warp & 3;
    const int bm = blockIdx.y * 128;
    const int bn = blockIdx.x * 128;

    if (tid < 128) sbias[tid] = latent_bias[bn + tid];

    float acc[4][4][4];
    #pragma unroll
    for (int mt = 0; mt < 4; mt++)
        #pragma unroll
        for (int nt = 0; nt < 4; nt++)
            #pragma unroll
            for (int q = 0; q < 4; q++) acc[mt][nt][q] = 0.f;

    const int r0 = tid >> 1, q0 = (tid & 1) << 1;

    auto stage = [&](int buf, int kc) {
        uint32_t b = bufs + buf * BUFB;
        #pragma unroll
        for (int t = 0; t < 2; t++) {
            int q = q0 + t;
            uint32_t dst = b + (uint32_t)(r0 * 80 + q * 16);
            size_t ga = (size_t)(bm + r0) * D_IN + kc + q * 8;
            size_t gb = (size_t)(bn + r0) * D_IN + kc + q * 8;
            CP16(dst, g_Xhi + ga);
            CP16(dst + ARR, g_Xlo + ga);
            CP16(dst + 2 * ARR, g_Whi + gb);
            CP16(dst + 3 * ARR, g_Wlo + gb);
        }
        CP_COMMIT();
    };

    const int a_r = lane & 15;
    const int a_c = (lane >> 4) << 3;
    const int b_r = (lane & 7) | ((lane >> 4) << 3);
    const int b_c = ((lane >> 3) & 1) << 3;

    stage(0, 0);
    #pragma unroll 1
    for (int c = 0; c < NCH; c++) {
        if (c + 1 < NCH) {
            stage((c + 1) & 1, (c + 1) * 32);
            asm volatile("cp.async.wait_group 1;" ::: "memory");
        } else {
            asm volatile("cp.async.wait_group 0;" ::: "memory");
        }
        __syncthreads();

        const uint32_t Ab = bufs + (c & 1) * BUFB;
        const uint32_t Bb = Ab + 2 * ARR;
        #pragma unroll
        for (int kk = 0; kk < 32; kk += 16) {
            unsigned bh[2][4], bl[2][4];
            #pragma unroll
            for (int ntp = 0; ntp < 2; ntp++) {
                uint32_t ba = Bb + (uint32_t)(((wn * 32 + ntp * 16 + b_r) * SMS + kk + b_c) * 2);
                ldsm_x4(bh[ntp], ba);
                ldsm_x4(bl[ntp], ba + ARR);
            }
            #pragma unroll
            for (int mt = 0; mt < 4; mt++) {
                uint32_t aa = Ab + (uint32_t)(((wm * 64 + mt * 16 + a_r) * SMS + kk + a_c) * 2);
                unsigned ah[4], al[4];
                ldsm_x4(ah, aa);
                ldsm_x4(al, aa + ARR);
                #pragma unroll
                for (int nt = 0; nt < 4; nt++) {
                    const unsigned* bhp = &bh[nt >> 1][(nt & 1) * 2];
                    const unsigned* blp = &bl[nt >> 1][(nt & 1) * 2];
                    mma16816(acc[mt][nt], ah, bhp);
                    mma16816(acc[mt][nt], ah, blp);
                    mma16816(acc[mt][nt], al, bhp);
                }
            }
        }
        __syncthreads();
    }

    #pragma unroll
    for (int nt = 0; nt < 4; nt++) {
        int col = bn + wn * 32 + nt * 8 + 2 * tig;
        float lb0 = sbias[col - bn], lb1 = sbias[col - bn + 1];
        #pragma unroll
        for (int mt = 0; mt < 4; mt++) {
            int row = bm + wm * 64 + mt * 16 + g;
            float2 v0 = make_float2(acc[mt][nt][0] + lb0, acc[mt][nt][1] + lb1);
            float2 v1 = make_float2(acc[mt][nt][2] + lb0, acc[mt][nt][3] + lb1);
            *(float2*)&out[(size_t)row * D_HID + col] = v0;
            *(float2*)&out[(size_t)(row + 8) * D_HID + col] = v1;
        }
    }
}

// -------------------- key transforms --------------------
__device__ __forceinline__ unsigned to_key(float f) {
    unsigned u = __float_as_uint(f);
    return u ^ (((unsigned)((int)u >> 31)) | 0x80000000u);
}
__device__ __forceinline__ float from_key(unsigned k) {
    unsigned u = (k & 0x80000000u) ? (k ^ 0x80000000u) : ~k;
    return __uint_as_float(u);
}

// -------------------- K3: topk select (2-pass radix) + fused h/f row zeroing --------------
__global__ __launch_bounds__(512)
void topk_select_kernel(const float* __restrict__ pre,
                        float* __restrict__ hOut,
                        float* __restrict__ fOut) {
    extern __shared__ unsigned keys[];    // 12288 keys (48 KB)
    __shared__ unsigned hist[256];
    __shared__ int s_b1, s_want2, s_prefix, s_cnt;

    const int tid = threadIdx.x;
    const int row = blockIdx.x;
    const float* prow = pre + (size_t)row * D_HID;
    int* cand = g_cand + (size_t)row * NCAND;

    if (tid == 0) s_cnt = 0;
    if (tid < 256) hist[tid] = 0;
    __syncthreads();

    // fused: load keys + pass-1 histogram (bits [31:24])
    for (int i = tid; i < D_HID; i += 512) {
        unsigned k = to_key(prow[i]);
        keys[i] = k;
        unsigned bin = k >> 24;
        unsigned same = __match_any_sync(0xFFFFFFFFu, bin);
        int leader = __ffs(same) - 1;
        if ((tid & 31) == leader) atomicAdd(&hist[bin], __popc(same));
    }

    // fused zeroing of this row's h and f regions (streams while barriers/scan run)
    {
        float4 z = make_float4(0.f, 0.f, 0.f, 0.f);
        float4* hz = (float4*)(hOut + (size_t)row * D_HID);
        float4* fz = (float4*)(fOut + (size_t)row * D_HID);
        #pragma unroll 2
        for (int i = tid; i < D_HID / 4; i += 512) {
            hz[i] = z;
            fz[i] = z;
        }
    }
    __syncthreads();

    if (tid == 0) {
        int cum = 0, b = 255;
        for (; b >= 0; b--) { cum += (int)hist[b]; if (cum >= WANT) break; }
        s_b1 = b;
        s_want2 = WANT - (cum - (int)hist[b]);
    }
    __syncthreads();
    const unsigned b1 = (unsigned)s_b1;
    if (tid < 256) hist[tid] = 0;
    __syncthreads();

    // pass 2: among top-byte == b1, histogram bits [23:16]
    for (int i = tid; i < D_HID; i += 512) {
        unsigned k = keys[i];
        if ((k >> 24) == b1) atomicAdd(&hist[(k >> 16) & 255u], 1u);
    }
    __syncthreads();
    if (tid == 0) {
        int want2 = s_want2;
        int cum = 0, b = 255;
        for (; b >= 0; b--) { cum += (int)hist[b]; if (cum >= want2) break; }
        s_prefix = (int)((b1 << 8) | (unsigned)b);
    }
    __syncthreads();
    const unsigned prefix = (unsigned)s_prefix;

    // collect: strictly greater 16-bit prefix first (count < WANT guaranteed)
    for (int i = tid; i < D_HID; i += 512) {
        if ((keys[i] >> 16) > prefix) {
            int p = atomicAdd(&s_cnt, 1);
            if (p < NCAND) cand[p] = i;
        }
    }
    __syncthreads();
    // boundary bin appended, capped
    for (int i = tid; i < D_HID; i += 512) {
        if ((keys[i] >> 16) == prefix) {
            int p = atomicAdd(&s_cnt, 1);
            if (p < NCAND) cand[p] = i;
        }
    }
    __syncthreads();
    if (tid == 0) g_ccnt[row] = s_cnt < NCAND ? s_cnt : NCAND;
}

// -------------------- K5: fused refine {512,256} + sort + rms + scatter + decode ----------
__global__ __launch_bounds__(256)
void refine_decode_kernel(const float* __restrict__ X,
                          const float* __restrict__ W,
                          const float* __restrict__ latent_bias,
                          const float* __restrict__ pre_bias,
                          float* __restrict__ out) {
    __shared__ float xs[D_IN];
    __shared__ float sC1[NCAND], sC2[NCAND];
    __shared__ unsigned long long sk[NCAND];
    __shared__ float s_fv[TOPK_K];
    __shared__ int s_fx[TOPK_K];
    __shared__ float s_sumsq, s_rn;

    const int tid = threadIdx.x;
    const int row = blockIdx.x;
    const int warp = tid >> 5, lane = tid & 31;
    const int C = g_ccnt[row];
    const int* cand = g_cand + (size_t)row * NCAND;

    if (tid == 0) s_sumsq = 0.f;
    for (int i = tid; i < D_IN; i += 256) xs[i] = X[(size_t)row * D_IN + i];
    if (tid < NCAND) sk[tid] = 0ULL;
    __syncthreads();

    // warp-split bitwise {512,256} chains
    if (warp < 4) {
        const int c = warp * 32 + lane;
        if (c < C) {
            const float* wrow = W + (size_t)cand[c] * D_IN;
            float c1 = 0.f;
            #pragma unroll 2
            for (int k = 0; k < 512; k += 4) {
                float4 wv = *(const float4*)&wrow[k];
                c1 = __fmaf_rn(xs[k + 0], wv.x, c1);
                c1 = __fmaf_rn(xs[k + 1], wv.y, c1);
                c1 = __fmaf_rn(xs[k + 2], wv.z, c1);
                c1 = __fmaf_rn(xs[k + 3], wv.w, c1);
            }
            sC1[c] = c1;
        }
    } else {
        const int c = (warp - 4) * 32 + lane;
        if (c < C) {
            const float* wrow = W + (size_t)cand[c] * D_IN;
            float c2 = 0.f;
            #pragma unroll 2
            for (int k = 512; k < 768; k += 4) {
                float4 wv = *(const float4*)&wrow[k];
                c2 = __fmaf_rn(xs[k + 0], wv.x, c2);
                c2 = __fmaf_rn(xs[k + 1], wv.y, c2);
                c2 = __fmaf_rn(xs[k + 2], wv.z, c2);
                c2 = __fmaf_rn(xs[k + 3], wv.w, c2);
            }
            sC2[c] = c2;
        }
    }
    __syncthreads();

    if (tid < C) {
        float v = __fadd_rn(__fadd_rn(sC1[tid], sC2[tid]), latent_bias[cand[tid]]);
        sk[tid] = ((unsigned long long)to_key(v) << 32) |
                  (unsigned long long)(0xFFFFFFFFu - (unsigned)cand[tid]);
    }
    __syncthreads();

    // bitonic sort 128 desc (value desc, index asc)
    for (int size = 2; size <= NCAND; size <<= 1) {
        for (int stride = size >> 1; stride > 0; stride >>= 1) {
            if (tid < NCAND) {
                int partner = tid ^ stride;
                if (partner > tid) {
                    bool desc = ((tid & size) == 0);
                    unsigned long long a = sk[tid], b = sk[partner];
                    bool sw = desc ? (a < b) : (a > b);
                    if (sw) { sk[tid] = b; sk[partner] = a; }
                }
            }
            __syncthreads();
        }
    }

    float rv = 0.f; int idx = 0;
    if (tid < TOPK_K) {
        unsigned long long s = sk[tid];
        idx = (int)(0xFFFFFFFFu - (unsigned)(s & 0xFFFFFFFFull));
        float v = from_key((unsigned)(s >> 32));
        rv = fmaxf(v, 0.f);
        float v2 = rv * rv;
        #pragma unroll
        for (int o = 16; o; o >>= 1) v2 += __shfl_down_sync(0xFFFFFFFFu, v2, o);
        if (lane == 0) atomicAdd(&s_sumsq, v2);
    }
    __syncthreads();
    if (tid == 0) {
        float m = __fadd_rn(s_sumsq / (float)D_HID, 1e-8f);
        s_rn = __fdiv_rn(1.0f, __fsqrt_rn(m));
    }
    __syncthreads();

    if (tid < TOPK_K) {
        float fv = rv * s_rn;
        s_fv[tid] = fv;
        s_fx[tid] = idx;
        size_t so = (size_t)row * TOPK_K + tid;
        out[IDX_OFF + so] = (float)idx;
        size_t ho = (size_t)row * D_HID + idx;
        out[H_OFF + ho] = rv;
        out[F_OFF + ho] = fv;
    }
    __syncthreads();

    // ---- decode phase: threads 0..191, 4 cols each ----
    if (tid < 192) {
        const int d = tid * 4;
        float4 a0 = *(const float4*)&pre_bias[d];
        float4 a1 = make_float4(0.f, 0.f, 0.f, 0.f);
        float4 a2 = make_float4(0.f, 0.f, 0.f, 0.f);
        float4 a3 = make_float4(0.f, 0.f, 0.f, 0.f);
        #pragma unroll 4
        for (int k = 0; k < TOPK_K; k += 4) {
            float c0 = s_fv[k + 0], c1 = s_fv[k + 1], c2 = s_fv[k + 2], c3 = s_fv[k + 3];
            float4 w0 = *(const float4*)&g_WdT[(size_t)s_fx[k + 0] * D_IN + d];
            float4 w1 = *(const float4*)&g_WdT[(size_t)s_fx[k + 1] * D_IN + d];
            float4 w2 = *(const float4*)&g_WdT[(size_t)s_fx[k + 2] * D_IN + d];
            float4 w3 = *(const float4*)&g_WdT[(size_t)s_fx[k + 3] * D_IN + d];
            a0.x += c0 * w0.x; a0.y += c0 * w0.y; a0.z += c0 * w0.z; a0.w += c0 * w0.w;
            a1.x += c1 * w1.x; a1.y += c1 * w1.y; a1.z += c1 * w1.z; a1.w += c1 * w1.w;
            a2.x += c2 * w2.x; a2.y += c2 * w2.y; a2.z += c2 * w2.z; a2.w += c2 * w2.w;
            a3.x += c3 * w3.x; a3.y += c3 * w3.y; a3.z += c3 * w3.z; a3.w += c3 * w3.w;
        }
        float4 acc = make_float4((a0.x + a1.x) + (a2.x + a3.x),
                                 (a0.y + a1.y) + (a2.y + a3.y),
                                 (a0.z + a1.z) + (a2.z + a3.z),
                                 (a0.w + a1.w) + (a2.w + a3.w));
        float4 xv = make_float4(xs[d], xs[d + 1], xs[d + 2], xs[d + 3]);
        float4 r = make_float4(xv.x - acc.x, xv.y - acc.y, xv.z - acc.z, xv.w - acc.w);
        *(float4*)&out[XHAT_OFF + (size_t)row * D_IN + d] = acc;
        *(float4*)&out[RES_OFF  + (size_t)row * D_IN + d] = r;
    }
}

// -------------------- launch --------------------
extern "C" void kernel_launch(void* const* d_in, const int* in_sizes, int n_in,
                              void* d_out, int out_size) {
    const float* x           = (const float*)d_in[0];
    const float* W_enc       = (const float*)d_in[1];
    const float* W_dec       = (const float*)d_in[2];
    const float* pre_bias    = (const float*)d_in[3];
    const float* latent_bias = (const float*)d_in[4];
    float* out = (float*)d_out;

    static bool attr_set = false;
    if (!attr_set) {
        cudaFuncSetAttribute(topk_select_kernel, cudaFuncAttributeMaxDynamicSharedMemorySize,
                             D_HID * (int)sizeof(unsigned));
        cudaFuncSetAttribute(gemm_mma_kernel, cudaFuncAttributeMaxDynamicSharedMemorySize,
                             1024 + 2 * BUFB);
        attr_set = true;
    }

    convertX_kernel<<<B_ROWS, 256>>>(x, pre_bias);
    convertW_kernel<<<D_HID, 256>>>(W_enc);
    transpose_kernel<<<dim3(D_HID / 32, D_IN / 32), dim3(32, 8)>>>(W_dec);

    gemm_mma_kernel<<<dim3(D_HID / 128, B_ROWS / 128), 256, 1024 + 2 * BUFB>>>(
        latent_bias, out + PRE_OFF);

    topk_select_kernel<<<B_ROWS, 512, D_HID * sizeof(unsigned)>>>(
        out + PRE_OFF, out + H_OFF, out + F_OFF);

    refine_decode_kernel<<<B_ROWS, 256>>>(x, W_enc, latent_bias, pre_bias, out);
}

// round 17
// speedup vs baseline: 1.0524x; 1.0524x over previous
#include <cuda_runtime.h>
#include <cuda_bf16.h>
#include <cstdint>

// Problem constants
#define B_ROWS   8192
#define D_IN     768
#define D_HID    12288
#define TOPK_K   64
#define NCAND    128
#define WANT     72

// Output layout (floats): x_hat, residual, h, f, indices, pre_acts
#define XHAT_OFF 0LL
#define RES_OFF  6291456LL
#define H_OFF    12582912LL
#define F_OFF    113246208LL
#define IDX_OFF  213909504LL
#define PRE_OFF  214433792LL

// -------------------- device scratch --------------------
__device__ float g_WdT[(size_t)D_HID * D_IN];
__device__ int   g_cand[(size_t)B_ROWS * NCAND];
__device__ int   g_ccnt[B_ROWS];
// bf16 split operands for tensor-core encode GEMM
__device__ __nv_bfloat16 g_Xhi[(size_t)B_ROWS * D_IN];
__device__ __nv_bfloat16 g_Xlo[(size_t)B_ROWS * D_IN];
__device__ __nv_bfloat16 g_Whi[(size_t)D_HID * D_IN];
__device__ __nv_bfloat16 g_Wlo[(size_t)D_HID * D_IN];

// -------------------- helpers --------------------
__device__ __forceinline__ uint32_t smem_u32(const void* p) {
    uint32_t a;
    asm("{ .reg .u64 t; cvta.to.shared.u64 t, %1; cvt.u32.u64 %0, t; }" : "=r"(a) : "l"(p));
    return a;
}
#define CP16(dst, src) \
    asm volatile("cp.async.cg.shared.global [%0], [%1], 16;" :: "r"(dst), "l"(src) : "memory")
#define CP_COMMIT() asm volatile("cp.async.commit_group;" ::: "memory")

__device__ __forceinline__ void ldsm_x4(unsigned* r, uint32_t addr) {
    asm volatile("ldmatrix.sync.aligned.m8n8.x4.shared.b16 {%0,%1,%2,%3}, [%4];"
                 : "=r"(r[0]), "=r"(r[1]), "=r"(r[2]), "=r"(r[3]) : "r"(addr));
}
__device__ __forceinline__ void mma16816(float* c, const unsigned* a, const unsigned* b) {
    asm volatile(
        "mma.sync.aligned.m16n8k16.row.col.f32.bf16.bf16.f32 "
        "{%0,%1,%2,%3}, {%4,%5,%6,%7}, {%8,%9}, {%0,%1,%2,%3};"
        : "+f"(c[0]), "+f"(c[1]), "+f"(c[2]), "+f"(c[3])
        : "r"(a[0]), "r"(a[1]), "r"(a[2]), "r"(a[3]), "r"(b[0]), "r"(b[1]));
}

// -------------------- K0a: bf16 split conversions (X and W fused in one launch) ----------
__global__ void convert_kernel(const float* __restrict__ x,
                               const float* __restrict__ w,
                               const float* __restrict__ pre_bias) {
    const int b = blockIdx.x;
    if (b < B_ROWS) {
        const int row = b;
        for (int c = threadIdx.x; c < D_IN; c += 256) {
            float v = x[(size_t)row * D_IN + c] - pre_bias[c];
            __nv_bfloat16 hi = __float2bfloat16(v);
            float lo = v - __bfloat162float(hi);
            size_t o = (size_t)row * D_IN + c;
            g_Xhi[o] = hi;
            g_Xlo[o] = __float2bfloat16(lo);
        }
    } else {
        const int row = b - B_ROWS;
        for (int c = threadIdx.x; c < D_IN; c += 256) {
            float v = w[(size_t)row * D_IN + c];
            __nv_bfloat16 hi = __float2bfloat16(v);
            float lo = v - __bfloat162float(hi);
            size_t o = (size_t)row * D_IN + c;
            g_Whi[o] = hi;
            g_Wlo[o] = __float2bfloat16(lo);
        }
    }
}

// -------------------- K0b: transpose W_dec -> g_WdT --------------------
__global__ void transpose_kernel(const float* __restrict__ Wd) {
    __shared__ float tile[32][33];
    int x = blockIdx.x * 32 + threadIdx.x;
    int y = blockIdx.y * 32 + threadIdx.y;
    #pragma unroll
    for (int i = 0; i < 32; i += 8)
        tile[threadIdx.y + i][threadIdx.x] = Wd[(size_t)(y + i) * D_HID + x];
    __syncthreads();
    int xo = blockIdx.y * 32 + threadIdx.x;
    int yo = blockIdx.x * 32 + threadIdx.y;
    #pragma unroll
    for (int i = 0; i < 32; i += 8)
        g_WdT[(size_t)(yo + i) * D_IN + xo] = tile[threadIdx.x][threadIdx.y + i];
}

// -------------------- K1: HMMA encode GEMM (unchanged; measured tensor=57.6%) -------------
#define SMS    40
#define ARR    10240
#define BUFB   40960
#define NCH    24

__global__ __launch_bounds__(256, 2)
void gemm_mma_kernel(const float* __restrict__ latent_bias,
                     float* __restrict__ out) {
    extern __shared__ char dsm[];
    float* sbias = (float*)dsm;
    const uint32_t bufs = smem_u32(dsm) + 1024;

    const int tid = threadIdx.x;
    const int warp = tid >> 5, lane = tid & 31;
    const int g = lane >> 2, tig = lane & 3;
    const int wm = warp >> 2, wn = warp & 3;
    const int bm = blockIdx.y * 128;
    const int bn = blockIdx.x * 128;

    if (tid < 128) sbias[tid] = latent_bias[bn + tid];

    float acc[4][4][4];
    #pragma unroll
    for (int mt = 0; mt < 4; mt++)
        #pragma unroll
        for (int nt = 0; nt < 4; nt++)
            #pragma unroll
            for (int q = 0; q < 4; q++) acc[mt][nt][q] = 0.f;

    const int r0 = tid >> 1, q0 = (tid & 1) << 1;

    auto stage = [&](int buf, int kc) {
        uint32_t b = bufs + buf * BUFB;
        #pragma unroll
        for (int t = 0; t < 2; t++) {
            int q = q0 + t;
            uint32_t dst = b + (uint32_t)(r0 * 80 + q * 16);
            size_t ga = (size_t)(bm + r0) * D_IN + kc + q * 8;
            size_t gb = (size_t)(bn + r0) * D_IN + kc + q * 8;
            CP16(dst, g_Xhi + ga);
            CP16(dst + ARR, g_Xlo + ga);
            CP16(dst + 2 * ARR, g_Whi + gb);
            CP16(dst + 3 * ARR, g_Wlo + gb);
        }
        CP_COMMIT();
    };

    const int a_r = lane & 15;
    const int a_c = (lane >> 4) << 3;
    const int b_r = (lane & 7) | ((lane >> 4) << 3);
    const int b_c = ((lane >> 3) & 1) << 3;

    stage(0, 0);
    #pragma unroll 1
    for (int c = 0; c < NCH; c++) {
        if (c + 1 < NCH) {
            stage((c + 1) & 1, (c + 1) * 32);
            asm volatile("cp.async.wait_group 1;" ::: "memory");
        } else {
            asm volatile("cp.async.wait_group 0;" ::: "memory");
        }
        __syncthreads();

        const uint32_t Ab = bufs + (c & 1) * BUFB;
        const uint32_t Bb = Ab + 2 * ARR;
        #pragma unroll
        for (int kk = 0; kk < 32; kk += 16) {
            unsigned bh[2][4], bl[2][4];
            #pragma unroll
            for (int ntp = 0; ntp < 2; ntp++) {
                uint32_t ba = Bb + (uint32_t)(((wn * 32 + ntp * 16 + b_r) * SMS + kk + b_c) * 2);
                ldsm_x4(bh[ntp], ba);
                ldsm_x4(bl[ntp], ba + ARR);
            }
            #pragma unroll
            for (int mt = 0; mt < 4; mt++) {
                uint32_t aa = Ab + (uint32_t)(((wm * 64 + mt * 16 + a_r) * SMS + kk + a_c) * 2);
                unsigned ah[4], al[4];
                ldsm_x4(ah, aa);
                ldsm_x4(al, aa + ARR);
                #pragma unroll
                for (int nt = 0; nt < 4; nt++) {
                    const unsigned* bhp = &bh[nt >> 1][(nt & 1) * 2];
                    const unsigned* blp = &bl[nt >> 1][(nt & 1) * 2];
                    mma16816(acc[mt][nt], ah, bhp);
                    mma16816(acc[mt][nt], ah, blp);
                    mma16816(acc[mt][nt], al, bhp);
                }
            }
        }
        __syncthreads();
    }

    #pragma unroll
    for (int nt = 0; nt < 4; nt++) {
        int col = bn + wn * 32 + nt * 8 + 2 * tig;
        float lb0 = sbias[col - bn], lb1 = sbias[col - bn + 1];
        #pragma unroll
        for (int mt = 0; mt < 4; mt++) {
            int row = bm + wm * 64 + mt * 16 + g;
            float2 v0 = make_float2(acc[mt][nt][0] + lb0, acc[mt][nt][1] + lb1);
            float2 v1 = make_float2(acc[mt][nt][2] + lb0, acc[mt][nt][3] + lb1);
            *(float2*)&out[(size_t)row * D_HID + col] = v0;
            *(float2*)&out[(size_t)(row + 8) * D_HID + col] = v1;
        }
    }
}

// -------------------- key transforms --------------------
__device__ __forceinline__ unsigned to_key(float f) {
    unsigned u = __float_as_uint(f);
    return u ^ (((unsigned)((int)u >> 31)) | 0x80000000u);
}
__device__ __forceinline__ float from_key(unsigned k) {
    unsigned u = (k & 0x80000000u) ? (k ^ 0x80000000u) : ~k;
    return __uint_as_float(u);
}

// -------------------- K3: topk select, NO smem key array (3 global passes) ----------------
// Pass1: float4 read (DRAM) -> top-byte histogram; fused h/f zeroing.
// Pass2: re-read (L2) -> collect top-byte > b1; histogram bits[23:16] of ==b1.
// Pass3: re-read (L2) -> collect boundary bin (capped NCAND).
__global__ __launch_bounds__(512)
void topk_select_kernel(const float* __restrict__ pre,
                        float* __restrict__ hOut,
                        float* __restrict__ fOut) {
    __shared__ unsigned hist[256];
    __shared__ int s_b1, s_b2, s_cnt;

    const int tid = threadIdx.x;
    const int row = blockIdx.x;
    const float4* prow4 = (const float4*)(pre + (size_t)row * D_HID);
    int* cand = g_cand + (size_t)row * NCAND;

    if (tid == 0) s_cnt = 0;
    if (tid < 256) hist[tid] = 0;
    __syncthreads();

    // pass 1: histogram top byte + zero h/f
    {
        float4 z = make_float4(0.f, 0.f, 0.f, 0.f);
        float4* hz = (float4*)(hOut + (size_t)row * D_HID);
        float4* fz = (float4*)(fOut + (size_t)row * D_HID);
        #pragma unroll 1
        for (int i = tid; i < D_HID / 4; i += 512) {
            float4 v = prow4[i];
            hz[i] = z;
            fz[i] = z;
            atomicAdd(&hist[to_key(v.x) >> 24], 1u);
            atomicAdd(&hist[to_key(v.y) >> 24], 1u);
            atomicAdd(&hist[to_key(v.z) >> 24], 1u);
            atomicAdd(&hist[to_key(v.w) >> 24], 1u);
        }
    }
    __syncthreads();
    if (tid == 0) {
        int cum = 0, b = 255;
        for (; b >= 0; b--) { cum += (int)hist[b]; if (cum >= WANT) break; }
        s_b1 = b;
        s_b2 = WANT - (cum - (int)hist[b]);   // temporarily want2
    }
    __syncthreads();
    const unsigned b1 = (unsigned)s_b1;
    const int want2 = s_b2;
    if (tid < 256) hist[tid] = 0;
    __syncthreads();

    // pass 2: collect top-byte > b1; histogram second byte of == b1
    #pragma unroll 1
    for (int i = tid; i < D_HID / 4; i += 512) {
        float4 v = prow4[i];
        unsigned kk[4] = {to_key(v.x), to_key(v.y), to_key(v.z), to_key(v.w)};
        #pragma unroll
        for (int j = 0; j < 4; j++) {
            unsigned tb = kk[j] >> 24;
            if (tb > b1) {
                int p = atomicAdd(&s_cnt, 1);
                if (p < NCAND) cand[p] = i * 4 + j;
            } else if (tb == b1) {
                atomicAdd(&hist[(kk[j] >> 16) & 255u], 1u);
            }
        }
    }
    __syncthreads();
    if (tid == 0) {
        int cum = 0, b = 255;
        for (; b >= 0; b--) { cum += (int)hist[b]; if (cum >= want2) break; }
        s_b2 = b;
    }
    __syncthreads();
    const unsigned b2 = (unsigned)s_b2;

    // pass 3: collect top-byte == b1 && second byte >= b2 (capped)
    #pragma unroll 1
    for (int i = tid; i < D_HID / 4; i += 512) {
        float4 v = prow4[i];
        unsigned kk[4] = {to_key(v.x), to_key(v.y), to_key(v.z), to_key(v.w)};
        #pragma unroll
        for (int j = 0; j < 4; j++) {
            if ((kk[j] >> 24) == b1 && ((kk[j] >> 16) & 255u) >= b2) {
                int p = atomicAdd(&s_cnt, 1);
                if (p < NCAND) cand[p] = i * 4 + j;
            }
        }
    }
    __syncthreads();
    if (tid == 0) g_ccnt[row] = s_cnt < NCAND ? s_cnt : NCAND;
}

// -------------------- K5: fused refine {512,256} + sort + rms + scatter + decode ----------
__global__ __launch_bounds__(256)
void refine_decode_kernel(const float* __restrict__ X,
                          const float* __restrict__ W,
                          const float* __restrict__ latent_bias,
                          const float* __restrict__ pre_bias,
                          float* __restrict__ out) {
    __shared__ float xs[D_IN];
    __shared__ float sC1[NCAND], sC2[NCAND];
    __shared__ unsigned long long sk[NCAND];
    __shared__ float s_fv[TOPK_K];
    __shared__ int s_fx[TOPK_K];
    __shared__ float s_sumsq, s_rn;

    const int tid = threadIdx.x;
    const int row = blockIdx.x;
    const int warp = tid >> 5, lane = tid & 31;
    const int C = g_ccnt[row];
    const int* cand = g_cand + (size_t)row * NCAND;

    if (tid == 0) s_sumsq = 0.f;
    for (int i = tid; i < D_IN; i += 256) xs[i] = X[(size_t)row * D_IN + i];
    if (tid < NCAND) sk[tid] = 0ULL;
    __syncthreads();

    // warp-split bitwise {512,256} chains
    if (warp < 4) {
        const int c = warp * 32 + lane;
        if (c < C) {
            const float* wrow = W + (size_t)cand[c] * D_IN;
            float c1 = 0.f;
            #pragma unroll 2
            for (int k = 0; k < 512; k += 4) {
                float4 wv = *(const float4*)&wrow[k];
                c1 = __fmaf_rn(xs[k + 0], wv.x, c1);
                c1 = __fmaf_rn(xs[k + 1], wv.y, c1);
                c1 = __fmaf_rn(xs[k + 2], wv.z, c1);
                c1 = __fmaf_rn(xs[k + 3], wv.w, c1);
            }
            sC1[c] = c1;
        }
    } else {
        const int c = (warp - 4) * 32 + lane;
        if (c < C) {
            const float* wrow = W + (size_t)cand[c] * D_IN;
            float c2 = 0.f;
            #pragma unroll 2
            for (int k = 512; k < 768; k += 4) {
                float4 wv = *(const float4*)&wrow[k];
                c2 = __fmaf_rn(xs[k + 0], wv.x, c2);
                c2 = __fmaf_rn(xs[k + 1], wv.y, c2);
                c2 = __fmaf_rn(xs[k + 2], wv.z, c2);
                c2 = __fmaf_rn(xs[k + 3], wv.w, c2);
            }
            sC2[c] = c2;
        }
    }
    __syncthreads();

    if (tid < C) {
        float v = __fadd_rn(__fadd_rn(sC1[tid], sC2[tid]), latent_bias[cand[tid]]);
        sk[tid] = ((unsigned long long)to_key(v) << 32) |
                  (unsigned long long)(0xFFFFFFFFu - (unsigned)cand[tid]);
    }
    __syncthreads();

    // bitonic sort 128 desc (value desc, index asc)
    for (int size = 2; size <= NCAND; size <<= 1) {
        for (int stride = size >> 1; stride > 0; stride >>= 1) {
            if (tid < NCAND) {
                int partner = tid ^ stride;
                if (partner > tid) {
                    bool desc = ((tid & size) == 0);
                    unsigned long long a = sk[tid], b = sk[partner];
                    bool sw = desc ? (a < b) : (a > b);
                    if (sw) { sk[tid] = b; sk[partner] = a; }
                }
            }
            __syncthreads();
        }
    }

    float rv = 0.f; int idx = 0;
    if (tid < TOPK_K) {
        unsigned long long s = sk[tid];
        idx = (int)(0xFFFFFFFFu - (unsigned)(s & 0xFFFFFFFFull));
        float v = from_key((unsigned)(s >> 32));
        rv = fmaxf(v, 0.f);
        float v2 = rv * rv;
        #pragma unroll
        for (int o = 16; o; o >>= 1) v2 += __shfl_down_sync(0xFFFFFFFFu, v2, o);
        if (lane == 0) atomicAdd(&s_sumsq, v2);
    }
    __syncthreads();
    if (tid == 0) {
        float m = __fadd_rn(s_sumsq / (float)D_HID, 1e-8f);
        s_rn = __fdiv_rn(1.0f, __fsqrt_rn(m));
    }
    __syncthreads();

    if (tid < TOPK_K) {
        float fv = rv * s_rn;
        s_fv[tid] = fv;
        s_fx[tid] = idx;
        size_t so = (size_t)row * TOPK_K + tid;
        out[IDX_OFF + so] = (float)idx;
        size_t ho = (size_t)row * D_HID + idx;
        out[H_OFF + ho] = rv;
        out[F_OFF + ho] = fv;
    }
    __syncthreads();

    // ---- decode phase: threads 0..191, 4 cols each ----
    if (tid < 192) {
        const int d = tid * 4;
        float4 a0 = *(const float4*)&pre_bias[d];
        float4 a1 = make_float4(0.f, 0.f, 0.f, 0.f);
        float4 a2 = make_float4(0.f, 0.f, 0.f, 0.f);
        float4 a3 = make_float4(0.f, 0.f, 0.f, 0.f);
        #pragma unroll 4
        for (int k = 0; k < TOPK_K; k += 4) {
            float c0 = s_fv[k + 0], c1 = s_fv[k + 1], c2 = s_fv[k + 2], c3 = s_fv[k + 3];
            float4 w0 = *(const float4*)&g_WdT[(size_t)s_fx[k + 0] * D_IN + d];
            float4 w1 = *(const float4*)&g_WdT[(size_t)s_fx[k + 1] * D_IN + d];
            float4 w2 = *(const float4*)&g_WdT[(size_t)s_fx[k + 2] * D_IN + d];
            float4 w3 = *(const float4*)&g_WdT[(size_t)s_fx[k + 3] * D_IN + d];
            a0.x += c0 * w0.x; a0.y += c0 * w0.y; a0.z += c0 * w0.z; a0.w += c0 * w0.w;
            a1.x += c1 * w1.x; a1.y += c1 * w1.y; a1.z += c1 * w1.z; a1.w += c1 * w1.w;
            a2.x += c2 * w2.x; a2.y += c2 * w2.y; a2.z += c2 * w2.z; a2.w += c2 * w2.w;
            a3.x += c3 * w3.x; a3.y += c3 * w3.y; a3.z += c3 * w3.z; a3.w += c3 * w3.w;
        }
        float4 acc = make_float4((a0.x + a1.x) + (a2.x + a3.x),
                                 (a0.y + a1.y) + (a2.y + a3.y),
                                 (a0.z + a1.z) + (a2.z + a3.z),
                                 (a0.w + a1.w) + (a2.w + a3.w));
        float4 xv = make_float4(xs[d], xs[d + 1], xs[d + 2], xs[d + 3]);
        float4 r = make_float4(xv.x - acc.x, xv.y - acc.y, xv.z - acc.z, xv.w - acc.w);
        *(float4*)&out[XHAT_OFF + (size_t)row * D_IN + d] = acc;
        *(float4*)&out[RES_OFF  + (size_t)row * D_IN + d] = r;
    }
}

// -------------------- launch --------------------
extern "C" void kernel_launch(void* const* d_in, const int* in_sizes, int n_in,
                              void* d_out, int out_size) {
    const float* x           = (const float*)d_in[0];
    const float* W_enc       = (const float*)d_in[1];
    const float* W_dec       = (const float*)d_in[2];
    const float* pre_bias    = (const float*)d_in[3];
    const float* latent_bias = (const float*)d_in[4];
    float* out = (float*)d_out;

    static bool attr_set = false;
    if (!attr_set) {
        cudaFuncSetAttribute(gemm_mma_kernel, cudaFuncAttributeMaxDynamicSharedMemorySize,
                             1024 + 2 * BUFB);
        attr_set = true;
    }

    convert_kernel<<<B_ROWS + D_HID, 256>>>(x, W_enc, pre_bias);
    transpose_kernel<<<dim3(D_HID / 32, D_IN / 32), dim3(32, 8)>>>(W_dec);

    gemm_mma_kernel<<<dim3(D_HID / 128, B_ROWS / 128), 256, 1024 + 2 * BUFB>>>(
        latent_bias, out + PRE_OFF);

    topk_select_kernel<<<B_ROWS, 512>>>(out + PRE_OFF, out + H_OFF, out + F_OFF);

    refine_decode_kernel<<<B_ROWS, 256>>>(x, W_enc, latent_bias, pre_bias, out);
}